// round 7
// baseline (speedup 1.0000x reference)
#include <cuda_runtime.h>
#include <cuda_bf16.h>

// Shapes fixed by problem: T=1024, B=8, D=64, N=64
#define T_DIM 1024
#define B_DIM 8
#define CH    32                   // chunks over T
#define TC    (T_DIM / CH)         // 32 timesteps per chunk
#define EPSV  1e-8f

// Scratch (device globals, allocation-free)
__device__ float  gLogAgg[CH * B_DIM * 64];  // log of per-chunk alpha product
__device__ float4 gPfx[CH * B_DIM * 1024];   // inclusive scaled prefix tiles
__device__ int    gFlag[CH * B_DIM * 2];     // prefix-ready flags per (c,b,h)

__device__ __forceinline__ int ld_acq(const int* p) {
    int v;
    asm volatile("ld.acquire.gpu.b32 %0, [%1];" : "=r"(v) : "l"(p) : "memory");
    return v;
}
__device__ __forceinline__ void st_rel(int* p, int v) {
    asm volatile("st.release.gpu.b32 [%0], %1;" :: "l"(p), "r"(v) : "memory");
}

// ---------------------------------------------------------------------------
// K1: gLogAgg[c,b,n] = log( prod_t max(alpha,eps) ).  One logf per n.
// Also clears this (c,b)'s flags (graph replays). grid (CH,B), 256 threads.
// ---------------------------------------------------------------------------
__global__ void __launch_bounds__(256)
k_agg(const float* __restrict__ alpha) {
    const int c = blockIdx.x, b = blockIdx.y;
    const int tid = threadIdx.x;

    if (tid < 2) gFlag[(c * B_DIM + b) * 2 + tid] = 0;

    __shared__ float s_tot[4][64];

    const int tq = tid >> 6;     // 0..3, owns 8 timesteps
    const int n  = tid & 63;
    float r = 1.f;
#pragma unroll
    for (int i = 0; i < 8; i++) {
        int t = tq * 8 + i;
        r *= fmaxf(alpha[((c * TC + t) * B_DIM + b) * 64 + n], EPSV);
    }
    s_tot[tq][n] = r;
    __syncthreads();
    if (tid < 64) {
        gLogAgg[(c * B_DIM + b) * 64 + tid] =
            logf(s_tot[0][tid] * s_tot[1][tid] * s_tot[2][tid] * s_tot[3][tid]);
    }
}

// ---------------------------------------------------------------------------
// K2: grid (CH, B, 2) = 512 blocks, 512 threads. Block (c,b,h): h = d-half.
// Serial-carry prefix: wait only on (c-1)'s inclusive prefix tile.
// ---------------------------------------------------------------------------
__global__ void __launch_bounds__(512)
k_fused2(const float* __restrict__ vv,
         const float* __restrict__ kk,
         const float* __restrict__ alpha,
         float4* __restrict__ out) {
    const int c = blockIdx.x, b = blockIdx.y, h = blockIdx.z;
    const int tid = threadIdx.x;

    __shared__ float  s_v[TC][32];
    __shared__ float4 s_w4[TC][16];
    __shared__ float  s_scale[64];
    __shared__ float  s_tot[8][64];
    float* s_w = (float*)s_w4;

    // ---- Phase 0: own-chunk scale[n] = exp(pre_c)/(exp(total)+eps) ----
    if (tid < 64) {
        float run = 0.f, pre = 0.f;
#pragma unroll
        for (int cc = 0; cc < CH; cc++) {
            if (cc == c) pre = run;
            run += __ldg(&gLogAgg[(cc * B_DIM + b) * 64 + tid]);
        }
        s_scale[tid] = expf(pre) / (expf(run) + EPSV);
    }

    // ---- Phase 1a: v half-tile load ----
    for (int i = tid; i < TC * 32; i += 512) {
        int t = i >> 5, j = i & 31;
        s_v[t][j] = vv[((c * TC + t) * B_DIM + b) * 64 + h * 32 + j];
    }

    // ---- Phase 1b: chunk-local multiply-scan of clamped alpha ----
    const int tq = tid >> 6;     // 0..7, owns 4 consecutive timesteps
    const int n  = tid & 63;
    const int gbase = ((c * TC + tq * 4) * B_DIM + b) * 64 + n;  // +512 per t
    float p0, p1, p2, p3;
    {
        float r = fmaxf(alpha[gbase        ], EPSV); p0 = r;
        r      *= fmaxf(alpha[gbase +  512 ], EPSV); p1 = r;
        r      *= fmaxf(alpha[gbase + 1024 ], EPSV); p2 = r;
        r      *= fmaxf(alpha[gbase + 1536 ], EPSV); p3 = r;
        s_tot[tq][n] = r;
    }
    __syncthreads();
    if (tid < 64) {                      // exclusive product across the 8 groups
        float run = 1.f;
#pragma unroll
        for (int q = 0; q < 8; q++) { float x = s_tot[q][tid]; s_tot[q][tid] = run; run *= x; }
    }
    __syncthreads();
    {
        float off = s_tot[tq][n] * s_scale[n];   // group prefix * decay scale
        s_w[(tq * 4 + 0) * 64 + n] = kk[gbase        ] * (p0 * off);
        s_w[(tq * 4 + 1) * 64 + n] = kk[gbase +  512 ] * (p1 * off);
        s_w[(tq * 4 + 2) * 64 + n] = kk[gbase + 1024 ] * (p2 * off);
        s_w[(tq * 4 + 3) * 64 + n] = kk[gbase + 1536 ] * (p3 * off);
    }
    __syncthreads();

    // ---- Phase 2: own chunk outer sum C ----
    const int dl = tid >> 4;     // 0..31 local d row
    const int n4 = tid & 15;
    const int lane = (h * 32 + dl) * 16 + n4;
    float4 C = make_float4(0.f, 0.f, 0.f, 0.f);
#pragma unroll
    for (int t = 0; t < TC; t++) {
        float  v0 = s_v[t][dl];
        float4 w  = s_w4[t][n4];
        C.x += v0 * w.x; C.y += v0 * w.y; C.z += v0 * w.z; C.w += v0 * w.w;
    }

    // ---- Phase 3: serial-carry prefix over chunks ----
    float4 acc = make_float4(0.f, 0.f, 0.f, 0.f);     // exclusive prefix
    if (c > 0) {
        if (tid == 0) {
            while (ld_acq(&gFlag[((c - 1) * B_DIM + b) * 2 + h]) == 0) __nanosleep(20);
        }
        __syncthreads();
        acc = __ldcg(&gPfx[((c - 1) * B_DIM + b) * 1024 + lane]);
    }
    // publish inclusive prefix for successor
    {
        float4 incl = make_float4(acc.x + C.x, acc.y + C.y, acc.z + C.z, acc.w + C.w);
        gPfx[(c * B_DIM + b) * 1024 + lane] = incl;
    }
    __threadfence();
    __syncthreads();
    if (tid == 0) st_rel(&gFlag[(c * B_DIM + b) * 2 + h], 1);

    // ---- Phase 4: stream the 134 MB output from the exclusive prefix ----
#pragma unroll
    for (int t = 0; t < TC; t++) {
        float  vt = s_v[t][dl];
        float4 wt = s_w4[t][n4];
        acc.x += vt * wt.x;
        acc.y += vt * wt.y;
        acc.z += vt * wt.z;
        acc.w += vt * wt.w;
        out[((c * TC + t) * B_DIM + b) * 1024 + lane] = acc;
    }
}

// ---------------------------------------------------------------------------
extern "C" void kernel_launch(void* const* d_in, const int* in_sizes, int n_in,
                              void* d_out, int out_size) {
    (void)in_sizes; (void)n_in; (void)out_size;
    const float* v     = (const float*)d_in[0];
    const float* k     = (const float*)d_in[1];
    const float* alpha = (const float*)d_in[2];
    float4* out = (float4*)d_out;

    k_agg<<<dim3(CH, B_DIM), 256>>>(alpha);
    k_fused2<<<dim3(CH, B_DIM, 2), 512>>>(v, k, alpha, out);
}

// round 9
// speedup vs baseline: 2.2320x; 2.2320x over previous
#include <cuda_runtime.h>
#include <cuda_bf16.h>

// Shapes fixed by problem: T=1024, B=8, D=64, N=64
#define T_DIM 1024
#define B_DIM 8
#define CH    32                   // chunks over T
#define TC    (T_DIM / CH)         // 32 timesteps per chunk
#define EPSV  1e-8f

// Scratch (device globals, allocation-free)
__device__ float  gLogAgg[CH * B_DIM * 64];  // log of per-chunk alpha product
__device__ float  gWraw[T_DIM * B_DIM * 64]; // k * chunk-local cumprod (2 MB)
__device__ float4 gCraw[CH * B_DIM * 1024];  // unscaled chunk outer sums (4 MB)

// ---------------------------------------------------------------------------
// K1: per (c,b): chunk-local multiply-scan -> w_raw, chunk outer sums -> gCraw,
//     chunk log product -> gLogAgg. No cross-chunk dependencies.
// grid (CH,B), 512 threads.
// ---------------------------------------------------------------------------
__global__ void __launch_bounds__(512)
k_chunk(const float* __restrict__ vv,
        const float* __restrict__ kk,
        const float* __restrict__ alpha) {
    const int c = blockIdx.x, b = blockIdx.y;
    const int tid = threadIdx.x;

    __shared__ float  s_v[TC][64];
    __shared__ float4 s_w4[TC][16];
    __shared__ float  s_tot[8][64];
    float* s_w = (float*)s_w4;

    // v tile load (coalesced)
    for (int i = tid; i < TC * 64; i += 512) {
        int t = i >> 6, j = i & 63;
        s_v[t][j] = vv[((c * TC + t) * B_DIM + b) * 64 + j];
    }

    // chunk-local multiply-scan of clamped alpha; w_raw = k * localprod
    const int tq = tid >> 6;     // 0..7, owns 4 consecutive timesteps
    const int n  = tid & 63;
    const int gbase = ((c * TC + tq * 4) * B_DIM + b) * 64 + n;  // +512 per t
    float p0, p1, p2, p3;
    {
        float r = fmaxf(alpha[gbase        ], EPSV); p0 = r;
        r      *= fmaxf(alpha[gbase +  512 ], EPSV); p1 = r;
        r      *= fmaxf(alpha[gbase + 1024 ], EPSV); p2 = r;
        r      *= fmaxf(alpha[gbase + 1536 ], EPSV); p3 = r;
        s_tot[tq][n] = r;
    }
    __syncthreads();
    if (tid < 64) {                      // exclusive product across 8 groups
        float run = 1.f;
#pragma unroll
        for (int q = 0; q < 8; q++) { float x = s_tot[q][tid]; s_tot[q][tid] = run; run *= x; }
        gLogAgg[(c * B_DIM + b) * 64 + tid] = logf(run);
    }
    __syncthreads();
    {
        float off = s_tot[tq][n];        // exclusive group prefix (local only)
        float w0 = kk[gbase        ] * (p0 * off);
        float w1 = kk[gbase +  512 ] * (p1 * off);
        float w2 = kk[gbase + 1024 ] * (p2 * off);
        float w3 = kk[gbase + 1536 ] * (p3 * off);
        s_w[(tq * 4 + 0) * 64 + n] = w0;  gWraw[gbase        ] = w0;
        s_w[(tq * 4 + 1) * 64 + n] = w1;  gWraw[gbase +  512 ] = w1;
        s_w[(tq * 4 + 2) * 64 + n] = w2;  gWraw[gbase + 1024 ] = w2;
        s_w[(tq * 4 + 3) * 64 + n] = w3;  gWraw[gbase + 1536 ] = w3;
    }
    __syncthreads();

    // unscaled chunk outer sums (full d: two rows per thread)
    const int d  = tid >> 4;     // 0..31
    const int n4 = tid & 15;
    float4 a0 = make_float4(0.f, 0.f, 0.f, 0.f), a1 = a0;
#pragma unroll
    for (int t = 0; t < TC; t++) {
        float v0 = s_v[t][d], v1 = s_v[t][d + 32];
        float4 w = s_w4[t][n4];
        a0.x += v0 * w.x; a0.y += v0 * w.y; a0.z += v0 * w.z; a0.w += v0 * w.w;
        a1.x += v1 * w.x; a1.y += v1 * w.y; a1.z += v1 * w.z; a1.w += v1 * w.w;
    }
    int base = (c * B_DIM + b) * 1024;
    gCraw[base + d * 16 + n4]        = a0;
    gCraw[base + (d + 32) * 16 + n4] = a1;
}

// ---------------------------------------------------------------------------
// K2: scale table + prefix from gCraw + stream. No flags, no waits.
// grid (CH, B, 2) = 512 blocks, 512 threads. h selects d-half.
// ---------------------------------------------------------------------------
__global__ void __launch_bounds__(512)
k_stream(const float* __restrict__ vv, float4* __restrict__ out) {
    const int c = blockIdx.x, b = blockIdx.y, h = blockIdx.z;
    const int tid = threadIdx.x;

    __shared__ float  s_v[TC][32];
    __shared__ float4 s_w4[TC][16];
    __shared__ float4 s_sc4[CH][16];     // scale table over (cc, n) as float4
    float* s_w  = (float*)s_w4;
    float* s_sc = (float*)s_sc4;

    // issue tile loads first (latency)
    for (int i = tid; i < TC * 32; i += 512) {
        int t = i >> 5, j = i & 31;
        s_v[t][j] = vv[((c * TC + t) * B_DIM + b) * 64 + h * 32 + j];
    }
    for (int i = tid; i < TC * 64; i += 512) {
        int t = i >> 6, j = i & 63;
        s_w[t * 64 + j] = gWraw[((c * TC + t) * B_DIM + b) * 64 + j];
    }

    // scale table: scale_cc[n] = exp(pre_cc) / (exp(total)+eps)
    if (tid < 64) {
        float run = 0.f;
#pragma unroll
        for (int cc = 0; cc < CH; cc++) {
            s_sc[cc * 64 + tid] = expf(run);
            run += __ldg(&gLogAgg[(cc * B_DIM + b) * 64 + tid]);
        }
        float inv = 1.f / (expf(run) + EPSV);
#pragma unroll
        for (int cc = 0; cc < CH; cc++) s_sc[cc * 64 + tid] *= inv;
    }
    __syncthreads();

    // scale own chunk's w in smem
    for (int i = tid; i < TC * 64; i += 512) {
        s_w[i] *= s_sc[c * 64 + (i & 63)];
    }
    __syncthreads();

    const int dl = tid >> 4;     // 0..31 local d row
    const int n4 = tid & 15;
    const int lane = (h * 32 + dl) * 16 + n4;

    // exclusive prefix: acc = sum_{cc<c} scale_cc (.) Craw_cc   (pure L2 reads)
    float4 acc = make_float4(0.f, 0.f, 0.f, 0.f);
    for (int cc = 0; cc < c; cc++) {
        float4 x  = __ldg(&gCraw[(cc * B_DIM + b) * 1024 + lane]);
        float4 sc = s_sc4[cc][n4];
        acc.x += sc.x * x.x; acc.y += sc.y * x.y;
        acc.z += sc.z * x.z; acc.w += sc.w * x.w;
    }

    // stream the 134 MB output
#pragma unroll
    for (int t = 0; t < TC; t++) {
        float  vt = s_v[t][dl];
        float4 wt = s_w4[t][n4];
        acc.x += vt * wt.x;
        acc.y += vt * wt.y;
        acc.z += vt * wt.z;
        acc.w += vt * wt.w;
        out[((c * TC + t) * B_DIM + b) * 1024 + lane] = acc;
    }
}

// ---------------------------------------------------------------------------
extern "C" void kernel_launch(void* const* d_in, const int* in_sizes, int n_in,
                              void* d_out, int out_size) {
    (void)in_sizes; (void)n_in; (void)out_size;
    const float* v     = (const float*)d_in[0];
    const float* k     = (const float*)d_in[1];
    const float* alpha = (const float*)d_in[2];
    float4* out = (float4*)d_out;

    k_chunk<<<dim3(CH, B_DIM), 512>>>(v, k, alpha);
    k_stream<<<dim3(CH, B_DIM, 2), 512>>>(v, out);
}

// round 10
// speedup vs baseline: 2.2452x; 1.0059x over previous
#include <cuda_runtime.h>
#include <cuda_bf16.h>

// Shapes fixed by problem: T=1024, B=8, D=64, N=64
#define T_DIM 1024
#define B_DIM 8
#define CH    32                   // K1 chunks over T
#define TC    (T_DIM / CH)         // 32 timesteps per K1 chunk
#define SC    16                   // K2 super-chunks
#define TS    (T_DIM / SC)         // 64 timesteps per K2 block
#define EPSV  1e-8f

// Scratch (device globals, allocation-free)
__device__ float  gLogAgg[CH * B_DIM * 64];  // log of per-chunk alpha product
__device__ float  gWraw[T_DIM * B_DIM * 64]; // k * chunk-local cumprod (2 MB)
__device__ float4 gCraw[CH * B_DIM * 1024];  // unscaled chunk outer sums (4 MB)

// ---------------------------------------------------------------------------
// K1: per (c,b): chunk-local multiply-scan -> w_raw, chunk outer sums -> gCraw,
//     chunk log product -> gLogAgg. No cross-chunk dependencies.
// grid (CH,B), 512 threads.
// ---------------------------------------------------------------------------
__global__ void __launch_bounds__(512)
k_chunk(const float* __restrict__ vv,
        const float* __restrict__ kk,
        const float* __restrict__ alpha) {
    const int c = blockIdx.x, b = blockIdx.y;
    const int tid = threadIdx.x;

    __shared__ float  s_v[TC][64];
    __shared__ float4 s_w4[TC][16];
    __shared__ float  s_tot[8][64];
    float* s_w = (float*)s_w4;

    // v tile load (coalesced)
    for (int i = tid; i < TC * 64; i += 512) {
        int t = i >> 6, j = i & 63;
        s_v[t][j] = vv[((c * TC + t) * B_DIM + b) * 64 + j];
    }

    // chunk-local multiply-scan of clamped alpha; w_raw = k * localprod
    const int tq = tid >> 6;     // 0..7, owns 4 consecutive timesteps
    const int n  = tid & 63;
    const int gbase = ((c * TC + tq * 4) * B_DIM + b) * 64 + n;  // +512 per t
    float p0, p1, p2, p3;
    {
        float r = fmaxf(alpha[gbase        ], EPSV); p0 = r;
        r      *= fmaxf(alpha[gbase +  512 ], EPSV); p1 = r;
        r      *= fmaxf(alpha[gbase + 1024 ], EPSV); p2 = r;
        r      *= fmaxf(alpha[gbase + 1536 ], EPSV); p3 = r;
        s_tot[tq][n] = r;
    }
    __syncthreads();
    if (tid < 64) {                      // exclusive product across 8 groups
        float run = 1.f;
#pragma unroll
        for (int q = 0; q < 8; q++) { float x = s_tot[q][tid]; s_tot[q][tid] = run; run *= x; }
        gLogAgg[(c * B_DIM + b) * 64 + tid] = logf(run);
    }
    __syncthreads();
    {
        float off = s_tot[tq][n];        // exclusive group prefix (local only)
        float w0 = kk[gbase        ] * (p0 * off);
        float w1 = kk[gbase +  512 ] * (p1 * off);
        float w2 = kk[gbase + 1024 ] * (p2 * off);
        float w3 = kk[gbase + 1536 ] * (p3 * off);
        s_w[(tq * 4 + 0) * 64 + n] = w0;  gWraw[gbase        ] = w0;
        s_w[(tq * 4 + 1) * 64 + n] = w1;  gWraw[gbase +  512 ] = w1;
        s_w[(tq * 4 + 2) * 64 + n] = w2;  gWraw[gbase + 1024 ] = w2;
        s_w[(tq * 4 + 3) * 64 + n] = w3;  gWraw[gbase + 1536 ] = w3;
    }
    __syncthreads();

    // unscaled chunk outer sums (full d: two rows per thread)
    const int d  = tid >> 4;     // 0..31
    const int n4 = tid & 15;
    float4 a0 = make_float4(0.f, 0.f, 0.f, 0.f), a1 = a0;
#pragma unroll
    for (int t = 0; t < TC; t++) {
        float v0 = s_v[t][d], v1 = s_v[t][d + 32];
        float4 w = s_w4[t][n4];
        a0.x += v0 * w.x; a0.y += v0 * w.y; a0.z += v0 * w.z; a0.w += v0 * w.w;
        a1.x += v1 * w.x; a1.y += v1 * w.y; a1.z += v1 * w.z; a1.w += v1 * w.w;
    }
    int base = (c * B_DIM + b) * 1024;
    gCraw[base + d * 16 + n4]        = a0;
    gCraw[base + (d + 32) * 16 + n4] = a1;
}

// ---------------------------------------------------------------------------
// K2: scale table (MLP loads) + prefix from gCraw + stream 64 timesteps.
// grid (SC, B, 2) = 256 blocks, 512 threads. h selects d-half.
// ---------------------------------------------------------------------------
__global__ void __launch_bounds__(512)
k_stream(const float* __restrict__ vv, float4* __restrict__ out) {
    const int c2 = blockIdx.x, b = blockIdx.y, h = blockIdx.z;
    const int tid = threadIdx.x;

    __shared__ float  s_v[TS][32];       // 8 KB
    __shared__ float4 s_w4[TS][16];      // 16 KB
    __shared__ float4 s_sc4[CH][16];     // 8 KB scale table (cc, n)
    float* s_w  = (float*)s_w4;
    float* s_sc = (float*)s_sc4;

    const int t0 = c2 * TS;

    // issue tile loads first (latency overlap with scale table)
    for (int i = tid; i < TS * 32; i += 512) {
        int t = i >> 5, j = i & 31;
        s_v[t][j] = vv[((t0 + t) * B_DIM + b) * 64 + h * 32 + j];
    }
    for (int i = tid; i < TS * 64; i += 512) {
        int t = i >> 6, j = i & 63;
        s_w[i] = gWraw[((t0 + t) * B_DIM + b) * 64 + j];
    }

    // scale table: MLP-parallel aggregate loads, then register scan
    if (tid < 64) {
        float a[CH];
#pragma unroll
        for (int cc = 0; cc < CH; cc++)
            a[cc] = __ldg(&gLogAgg[(cc * B_DIM + b) * 64 + tid]);
        float run = 0.f;
#pragma unroll
        for (int cc = 0; cc < CH; cc++) { s_sc[cc * 64 + tid] = expf(run); run += a[cc]; }
        float inv = 1.f / (expf(run) + EPSV);
#pragma unroll
        for (int cc = 0; cc < CH; cc++) s_sc[cc * 64 + tid] *= inv;
    }
    __syncthreads();

    // scale w in smem: first 32 t use chunk 2*c2, next 32 use 2*c2+1
    for (int i = tid; i < TS * 64; i += 512) {
        int cc = c2 * 2 + ((i >> 6) >> 5);
        s_w[i] *= s_sc[cc * 64 + (i & 63)];
    }
    __syncthreads();

    const int dl = tid >> 4;     // 0..31 local d row
    const int n4 = tid & 15;
    const int lane = (h * 32 + dl) * 16 + n4;

    // exclusive prefix: sum over K1 chunks before this super-chunk (MLP reads)
    float4 acc = make_float4(0.f, 0.f, 0.f, 0.f);
    for (int cc = 0; cc < c2 * 2; cc++) {
        float4 x  = __ldg(&gCraw[(cc * B_DIM + b) * 1024 + lane]);
        float4 sc = s_sc4[cc][n4];
        acc.x += sc.x * x.x; acc.y += sc.y * x.y;
        acc.z += sc.z * x.z; acc.w += sc.w * x.w;
    }

    // stream 64 timesteps (512 KB per block)
#pragma unroll
    for (int t = 0; t < TS; t++) {
        float  vt = s_v[t][dl];
        float4 wt = s_w4[t][n4];
        acc.x += vt * wt.x;
        acc.y += vt * wt.y;
        acc.z += vt * wt.z;
        acc.w += vt * wt.w;
        out[((t0 + t) * B_DIM + b) * 1024 + lane] = acc;
    }
}

// ---------------------------------------------------------------------------
extern "C" void kernel_launch(void* const* d_in, const int* in_sizes, int n_in,
                              void* d_out, int out_size) {
    (void)in_sizes; (void)n_in; (void)out_size;
    const float* v     = (const float*)d_in[0];
    const float* k     = (const float*)d_in[1];
    const float* alpha = (const float*)d_in[2];
    float4* out = (float4*)d_out;

    k_chunk<<<dim3(CH, B_DIM), 512>>>(v, k, alpha);
    k_stream<<<dim3(SC, B_DIM, 2), 512>>>(v, out);
}